// round 9
// baseline (speedup 1.0000x reference)
#include <cuda_runtime.h>
#include <cuda_bf16.h>
#include <cstdint>

// ---------------------------------------------------------------- constants
#define B_   64
#define T_   1000
#define I_   512
#define O_   256
#define M_   (B_ * T_)          // 64000
#define ALPHA 0.95f
#define BETA  0.9f

// GEMM tiling
#define BM      128
#define BN      256             // full O per CTA -> A loaded/split once
#define BKC     64              // K per chunk
#define NCHUNK  (I_ / BKC)      // 8
#define LDROW   144             // padded row stride in bytes (72 bf16)

// Scan chunking
#define SC_C    8
#define SC_L    (T_ / SC_C)     // 125

// SMEM: one stage = A hi/lo (128x144 each) + W hi/lo (256x144 each)
#define SA_HI   0
#define SA_LO   18432
#define SW_HI   36864
#define SW_LO   73728
#define STAGE   110592
#define SM_GTOT (2 * STAGE)     // 221184 <= 227KB opt-in

// ---------------------------------------------------------------- scratch
__device__ float g_h[(size_t)M_ * O_];                  // GEMM output
__device__ __nv_bfloat16 g_Whi[(size_t)O_ * I_];        // W hi (row-major [O][I])
__device__ __nv_bfloat16 g_Wlo[(size_t)O_ * I_];        // W lo

// ---------------------------------------------------------------- helpers
__device__ __forceinline__ uint32_t smem_u32(const void* p) {
    uint32_t a;
    asm("{ .reg .u64 t; cvta.to.shared.u64 t, %1; cvt.u32.u64 %0, t; }"
        : "=r"(a) : "l"(p));
    return a;
}
__device__ __forceinline__ void ldsm4(uint32_t* r, uint32_t a) {
    asm volatile("ldmatrix.sync.aligned.m8n8.x4.shared.b16 {%0,%1,%2,%3}, [%4];"
        : "=r"(r[0]), "=r"(r[1]), "=r"(r[2]), "=r"(r[3]) : "r"(a));
}
__device__ __forceinline__ void cp16(uint32_t d, const void* s) {
    asm volatile("cp.async.cg.shared.global [%0], [%1], 16;" :: "r"(d), "l"(s));
}
__device__ __forceinline__ void mma16816(float* d, const uint32_t* a,
                                         const uint32_t* b) {
    asm volatile("mma.sync.aligned.m16n8k16.row.col.f32.bf16.bf16.f32 "
        "{%0,%1,%2,%3}, {%4,%5,%6,%7}, {%8,%9}, {%0,%1,%2,%3};"
        : "+f"(d[0]), "+f"(d[1]), "+f"(d[2]), "+f"(d[3])
        : "r"(a[0]), "r"(a[1]), "r"(a[2]), "r"(a[3]), "r"(b[0]), "r"(b[1]));
}

// ---------------------------------------------------------------- W pre-split
__global__ void snn_wsplit(const float* __restrict__ W)
{
    int idx = blockIdx.x * blockDim.x + threadIdx.x;
    if (idx >= O_ * I_) return;
    float x = W[idx];
    __nv_bfloat16 hi = __float2bfloat16(x);
    __nv_bfloat16 lo = __float2bfloat16(x - __bfloat162float(hi));
    g_Whi[idx] = hi;
    g_Wlo[idx] = lo;
}

// ---------------------------------------------------------------- mma GEMM
// C[128,256] per CTA, 512 threads, 16 warps (4x4), warp tile 32x64.
// 3-term bf16 split: Ahi*Whi + Ahi*Wlo + Alo*Whi.
// Double-buffered stages; cp.async W + LDG A for chunk c+1 overlap compute(c).
__global__ __launch_bounds__(512, 1)
void snn_gemm_mma(const float* __restrict__ A)
{
    extern __shared__ char smem[];
    const uint32_t sb = smem_u32(smem);
    const int tid  = threadIdx.x;
    const int lane = tid & 31;
    const int wid  = tid >> 5;                  // 0..15
    const int wm   = wid >> 2;                  // 0..3  (M warps)
    const int wn   = wid & 3;                   // 0..3  (N warps)
    const int m0   = blockIdx.x * BM;

    // A staging: thread owns row = tid>>2, 16-float quarter = (tid&3)*16
    const int arow = tid >> 2;
    const int aq   = (tid & 3) * 16;
    const float* Ap = A + (size_t)(m0 + arow) * I_ + aq;
    const uint32_t a_sts = (uint32_t)arow * LDROW + aq * 2;

    // W staging: 2048 cp16 per tile (256 rows x 8); thread does 4 per tile
    // ldmatrix per-lane coords
    const int a_r = wm * 32 + (lane & 15);
    const int a_c = (lane >> 4) * 8;
    const int b_r = wn * 64 + (lane & 15);
    const int b_c = (lane >> 4) * 8;

    float acc[2][8][4];
    #pragma unroll
    for (int mb = 0; mb < 2; mb++)
        #pragma unroll
        for (int j = 0; j < 8; j++)
            #pragma unroll
            for (int q = 0; q < 4; q++) acc[mb][j][q] = 0.0f;

    float4 av[4];

    // ---- stage W for a chunk into buffer base
    auto stageW = [&](int chunk, uint32_t bufb) {
        #pragma unroll
        for (int i = 0; i < 4; i++) {
            int idx = tid + i * 512;            // 0..2047
            int row = idx >> 3, c = idx & 7;
            uint32_t doff = (uint32_t)row * LDROW + c * 16;
            size_t soff = (size_t)row * I_ + chunk * BKC + c * 8;
            cp16(sb + bufb + SW_HI + doff, g_Whi + soff);
            cp16(sb + bufb + SW_LO + doff, g_Wlo + soff);
        }
        asm volatile("cp.async.commit_group;" ::: "memory");
    };
    // ---- convert + STS prefetched A regs into buffer base
    auto stsA = [&](uint32_t bufb) {
        #pragma unroll
        for (int i = 0; i < 4; i++) {
            float4 v = av[i];
            __nv_bfloat162 h01 = __floats2bfloat162_rn(v.x, v.y);
            __nv_bfloat162 h23 = __floats2bfloat162_rn(v.z, v.w);
            __nv_bfloat162 l01 = __floats2bfloat162_rn(v.x - __low2float(h01),
                                                       v.y - __high2float(h01));
            __nv_bfloat162 l23 = __floats2bfloat162_rn(v.z - __low2float(h23),
                                                       v.w - __high2float(h23));
            *(uint2*)(smem + bufb + SA_HI + a_sts + i * 8) =
                make_uint2(*(uint32_t*)&h01, *(uint32_t*)&h23);
            *(uint2*)(smem + bufb + SA_LO + a_sts + i * 8) =
                make_uint2(*(uint32_t*)&l01, *(uint32_t*)&l23);
        }
    };

    // ---- prologue: stage chunk 0
    stageW(0, 0);
    {
        const float4* Ac = (const float4*)Ap;
        #pragma unroll
        for (int i = 0; i < 4; i++) av[i] = Ac[i];
    }
    stsA(0);

    #pragma unroll 1
    for (int chunk = 0; chunk < NCHUNK; chunk++) {
        const uint32_t bufb  = (chunk & 1) ? STAGE : 0;
        const uint32_t nbufb = STAGE - bufb;

        asm volatile("cp.async.wait_group 0;" ::: "memory");
        __syncthreads();   // W(c) landed; A(c) STS visible; buf^1 free

        // issue next-stage loads (overlap with compute below)
        if (chunk + 1 < NCHUNK) {
            stageW(chunk + 1, nbufb);
            const float4* Ac = (const float4*)(Ap + (chunk + 1) * BKC);
            #pragma unroll
            for (int i = 0; i < 4; i++) av[i] = Ac[i];
        }

        // ---- compute chunk on tensor pipe
        #pragma unroll
        for (int ks = 0; ks < 4; ks++) {
            const int kb = ks * 16;
            uint32_t ahi[2][4], alo[2][4];
            #pragma unroll
            for (int mb = 0; mb < 2; mb++) {
                uint32_t ra = sb + bufb + SA_HI
                            + (uint32_t)(a_r + mb * 16) * LDROW + (kb + a_c) * 2;
                ldsm4(ahi[mb], ra);
                ldsm4(alo[mb], ra + (SA_LO - SA_HI));
            }
            #pragma unroll
            for (int g = 0; g < 4; g++) {
                uint32_t rb = sb + bufb + SW_HI
                            + (uint32_t)(b_r + g * 16) * LDROW + (kb + b_c) * 2;
                uint32_t rh[4], rl[4];
                ldsm4(rh, rb);
                ldsm4(rl, rb + (SW_LO - SW_HI));
                uint32_t bhi0[2] = {rh[0], rh[2]}, bhi1[2] = {rh[1], rh[3]};
                uint32_t blo0[2] = {rl[0], rl[2]}, blo1[2] = {rl[1], rl[3]};
                #pragma unroll
                for (int mb = 0; mb < 2; mb++) {
                    mma16816(acc[mb][g*2],   ahi[mb], bhi0);
                    mma16816(acc[mb][g*2],   ahi[mb], blo0);
                    mma16816(acc[mb][g*2],   alo[mb], bhi0);
                    mma16816(acc[mb][g*2+1], ahi[mb], bhi1);
                    mma16816(acc[mb][g*2+1], ahi[mb], blo1);
                    mma16816(acc[mb][g*2+1], alo[mb], bhi1);
                }
            }
        }

        // ---- store next A chunk into the buffer just fetched into
        if (chunk + 1 < NCHUNK) stsA(nbufb);
    }

    // ---- epilogue: fragments -> g_h
    #pragma unroll
    for (int mb = 0; mb < 2; mb++) {
        int row = m0 + wm * 32 + mb * 16 + (lane >> 2);
        #pragma unroll
        for (int j = 0; j < 8; j++) {
            int col = wn * 64 + j * 8 + (lane & 3) * 2;
            float* p = g_h + (size_t)row * O_ + col;
            *(float2*)p            = make_float2(acc[mb][j][0], acc[mb][j][1]);
            *(float2*)(p + 8 * O_) = make_float2(acc[mb][j][2], acc[mb][j][3]);
        }
    }
}

// ---------------------------------------------------------------- parallel scan
// Chunked affine-scan: phase1 zero-init chunk scans, phase2 combine (8 states),
// phase3 exact re-scan with true init. Block = 32 chains x 8 chunks.
__global__ __launch_bounds__(256)
void snn_scan2(float* __restrict__ Y)
{
    __shared__ float ef[SC_C][32], eo[SC_C][32];
    __shared__ float qf[SC_C][32], qo[SC_C][32];

    const int tid = threadIdx.x;
    const int ch  = tid & 31;
    const int c   = tid >> 5;
    const int chain = blockIdx.x * 32 + ch;
    const int b = chain >> 8;
    const int o = chain & (O_ - 1);

    const float* hp = g_h + ((size_t)b * T_ + (size_t)c * SC_L) * O_ + o;

    float f = 0.0f, u = 0.0f;
    #pragma unroll 5
    for (int j = 0; j < SC_L; j++) {
        float h  = hp[(size_t)j * O_];
        float nu = fmaf(BETA, u, f);
        f = fmaf(ALPHA, f, h);
        u = nu;
    }
    ef[c][ch] = f;
    eo[c][ch] = u;
    __syncthreads();

    if (tid < 32) {
        float AL = 1.0f, BL = 1.0f;
        #pragma unroll
        for (int i = 0; i < SC_L; i++) { AL *= ALPHA; BL *= BETA; }
        const float GL = (AL - BL) * (1.0f / (ALPHA - BETA));
        float sf = 0.0f, su = 0.0f;
        #pragma unroll
        for (int cc = 0; cc < SC_C; cc++) {
            qf[cc][tid] = sf;
            qo[cc][tid] = su;
            float nsf = AL * sf + ef[cc][tid];
            float nsu = GL * sf + BL * su + eo[cc][tid];
            sf = nsf;
            su = nsu;
        }
    }
    __syncthreads();

    f = qf[c][ch];
    u = qo[c][ch];
    float* yp = Y + ((size_t)b * T_ + (size_t)c * SC_L) * O_ + o;
    #pragma unroll 5
    for (int j = 0; j < SC_L; j++) {
        float h  = hp[(size_t)j * O_];
        float nu = fmaf(BETA, u, f);
        f = fmaf(ALPHA, f, h);
        u = nu;
        yp[(size_t)j * O_] = nu;
    }
}

// ----------------------------------------------------------------
extern "C" void kernel_launch(void* const* d_in, const int* in_sizes, int n_in,
                              void* d_out, int out_size)
{
    const float* inputs = (const float*)d_in[0];   // (B,T,I) fp32
    const float* W      = (const float*)d_in[1];   // (O,I)   fp32
    float* out          = (float*)d_out;           // (B,T,O) fp32

    cudaFuncSetAttribute(snn_gemm_mma,
                         cudaFuncAttributeMaxDynamicSharedMemorySize, SM_GTOT);

    snn_wsplit<<<(O_ * I_ + 255) / 256, 256>>>(W);
    snn_gemm_mma<<<M_ / BM, 512, SM_GTOT>>>(inputs);
    snn_scan2<<<(B_ * O_) / 32, 256>>>(out);
}